// round 14
// baseline (speedup 1.0000x reference)
#include <cuda_runtime.h>
#include <cstdint>

#define L 16384
#define THREADS 1024
#define R 16

// Row-A swizzle (bijection on [0,16384)).
__device__ __forceinline__ int phA(int i) { return i ^ ((i >> 4) & 31); }
// Row-B swizzle: same family, extra constant XOR 21. Still a bijection and
// still conflict-free (constant XOR = bank permutation). Deliberately yields
// DIFFERENT address values than phA so ptxas cannot CSE row-A addresses and
// hold them live across row A's section for reuse in row B (the spill source).
__device__ __forceinline__ int phB(int i) { return i ^ ((((i >> 4) & 31)) ^ 21); }

// Named barrier over an aligned 256-thread (8-warp) group.
__device__ __forceinline__ void bar256(int gid) {
    asm volatile("bar.sync %0, %1;" :: "r"(gid + 1), "r"(256) : "memory");
}

// Packed butterfly: (a, b) <- (a+b, a-b) elementwise on float2 (sm_100+ f32x2).
__device__ __forceinline__ void bfly2(float2& a, float2& b) {
    unsigned long long A = *reinterpret_cast<unsigned long long*>(&a);
    unsigned long long B = *reinterpret_cast<unsigned long long*>(&b);
    unsigned long long S, D;
    asm("add.rn.f32x2 %0, %1, %2;" : "=l"(S) : "l"(A), "l"(B));
    asm("sub.rn.f32x2 %0, %1, %2;" : "=l"(D) : "l"(A), "l"(B));
    a = *reinterpret_cast<float2*>(&S);
    b = *reinterpret_cast<float2*>(&D);
}

__device__ __forceinline__ void bf_d1(float2 w[8]) {
#pragma unroll
    for (int j = 0; j < 8; j++) {
        float a = w[j].x, b = w[j].y;
        w[j].x = a + b;
        w[j].y = a - b;
    }
}

template <int D2>
__device__ __forceinline__ void bf_pk(float2 w[8]) {
#pragma unroll
    for (int j = 0; j < 8; j++)
        if ((j & D2) == 0) bfly2(w[j], w[j + D2]);
}

// Full 4-bit in-register FWHT (element bits 0..3): d=1,2,4,8.
__device__ __forceinline__ void fwht4(float2 w[8]) {
    bf_d1(w);
    bf_pk<1>(w);
    bf_pk<2>(w);
    bf_pk<4>(w);
}

extern __shared__ float sh[];

// Two rows per CTA, sequential per region (R10 schedule, proven 302us), with
// per-row swizzle constants + A/B section fences to kill the cross-row
// address-CSE register liveness that was spilling ~160MB to DRAM.
__global__ void __launch_bounds__(THREADS, 1) ff_kernel(
    const float* __restrict__ x,
    const float* __restrict__ Bv,
    const float* __restrict__ Gv,
    const int* __restrict__ Pi,
    float* __restrict__ out)
{
    const int t = threadIdx.x;
    // Pass element maps (identical to the proven kernels):
    //  P1: i = t*16 + r                      (bits 0-3)   exch -> P2: intra-warp
    //  P2: i = q*256 + r*16 + s, t=q*16+s    (bits 4-7)   exch -> P3: 256-thr group
    //  P3: i = u*4096 + r*256 + m, t=u*256+m (bits 8-11)  exch -> P4: CTA
    //  P4: i = (r&3)*4096 + (r>>2)*1024 + t  (bit12 in-float2, bit13 packed)
    const int q = t >> 4, s = t & 15;
    const int u = t >> 8, m = t & 255;

    const int rowA = blockIdx.x * 2;
    const float* xrA = x + (size_t)rowA * L;
    const float* xrB = xrA + L;
    float* outA = out + (size_t)rowA * L;
    float* outB = outA + L;

    float* const shA = sh;
    float* const shB = sh + L;

    float2 w[8];
    float* vf = reinterpret_cast<float*>(w);
    const int base = t * R;

    constexpr float SC = 1.0f / 16384.0f;

    // ---------- P1 + FWHT#1 bits 0-3 (row A, then row B) ----------
#pragma unroll
    for (int c = 0; c < 4; c++) {
        float4 xa = *reinterpret_cast<const float4*>(xrA + base + c * 4);
        float4 bv = *reinterpret_cast<const float4*>(Bv + base + c * 4);
        vf[c * 4 + 0] = xa.x * bv.x; vf[c * 4 + 1] = xa.y * bv.y;
        vf[c * 4 + 2] = xa.z * bv.z; vf[c * 4 + 3] = xa.w * bv.w;
    }
    fwht4(w);
#pragma unroll
    for (int r = 0; r < R; r++) shA[phA(base + r)] = vf[r];
    __syncwarp();                          // close row-A section
#pragma unroll
    for (int c = 0; c < 4; c++) {
        float4 xb = *reinterpret_cast<const float4*>(xrB + base + c * 4);
        float4 bv = *reinterpret_cast<const float4*>(Bv + base + c * 4);
        vf[c * 4 + 0] = xb.x * bv.x; vf[c * 4 + 1] = xb.y * bv.y;
        vf[c * 4 + 2] = xb.z * bv.z; vf[c * 4 + 3] = xb.w * bv.w;
    }
    fwht4(w);
#pragma unroll
    for (int r = 0; r < R; r++) shB[phB(base + r)] = vf[r];
    __syncwarp();                          // P1->P2 exchange is intra-warp

    // ---------- P2 (bits 4-7) ----------
#pragma unroll
    for (int r = 0; r < R; r++) vf[r] = shA[phA(q * 256 + r * 16 + s)];
    fwht4(w);
#pragma unroll
    for (int r = 0; r < R; r++) shA[phA(q * 256 + r * 16 + s)] = vf[r];
    __syncwarp();                          // close row-A section
#pragma unroll
    for (int r = 0; r < R; r++) vf[r] = shB[phB(q * 256 + r * 16 + s)];
    fwht4(w);
#pragma unroll
    for (int r = 0; r < R; r++) shB[phB(q * 256 + r * 16 + s)] = vf[r];
    bar256(u);                             // one barrier serves both rows

    // ---------- P3 (bits 8-11) ----------
#pragma unroll
    for (int r = 0; r < R; r++) vf[r] = shA[phA(u * 4096 + r * 256 + m)];
    fwht4(w);
#pragma unroll
    for (int r = 0; r < R; r++) shA[phA(u * 4096 + r * 256 + m)] = vf[r];
    __syncwarp();
#pragma unroll
    for (int r = 0; r < R; r++) vf[r] = shB[phB(u * 4096 + r * 256 + m)];
    fwht4(w);
#pragma unroll
    for (int r = 0; r < R; r++) shB[phB(u * 4096 + r * 256 + m)] = vf[r];
    __syncthreads();

    // ---------- P4 (bits 12-13) ----------
#pragma unroll
    for (int r = 0; r < R; r++) vf[r] = shA[phA((r & 3) * 4096 + (r >> 2) * 1024 + t)];
    bf_d1(w); bf_pk<1>(w);
#pragma unroll
    for (int r = 0; r < R; r++) shA[phA((r & 3) * 4096 + (r >> 2) * 1024 + t)] = vf[r];
    __syncwarp();
#pragma unroll
    for (int r = 0; r < R; r++) vf[r] = shB[phB((r & 3) * 4096 + (r >> 2) * 1024 + t)];
    bf_d1(w); bf_pk<1>(w);
#pragma unroll
    for (int r = 0; r < R; r++) shB[phB((r & 3) * 4096 + (r >> 2) * 1024 + t)] = vf[r];
    __syncthreads();                       // gather reads arbitrary positions

    // ---------- permutation gather + gain + FWHT#2-P1, row A ----------
#pragma unroll
    for (int c = 0; c < 4; c++) {
        int4   p = *reinterpret_cast<const int4*>(Pi + base + c * 4);
        float4 g = *reinterpret_cast<const float4*>(Gv + base + c * 4);
        vf[c * 4 + 0] = shA[phA(p.x)] * (g.x * SC);
        vf[c * 4 + 1] = shA[phA(p.y)] * (g.y * SC);
        vf[c * 4 + 2] = shA[phA(p.z)] * (g.z * SC);
        vf[c * 4 + 3] = shA[phA(p.w)] * (g.w * SC);
    }
    fwht4(w);
    __syncthreads();                       // all row-A gathers complete
#pragma unroll
    for (int r = 0; r < R; r++) shA[phA(base + r)] = vf[r];
    __syncwarp();

    // ---------- gather + FWHT#2-P1, row B ----------
#pragma unroll
    for (int c = 0; c < 4; c++) {
        int4   p = *reinterpret_cast<const int4*>(Pi + base + c * 4);
        float4 g = *reinterpret_cast<const float4*>(Gv + base + c * 4);
        vf[c * 4 + 0] = shB[phB(p.x)] * (g.x * SC);
        vf[c * 4 + 1] = shB[phB(p.y)] * (g.y * SC);
        vf[c * 4 + 2] = shB[phB(p.z)] * (g.z * SC);
        vf[c * 4 + 3] = shB[phB(p.w)] * (g.w * SC);
    }
    fwht4(w);
    __syncthreads();                       // all row-B gathers complete
#pragma unroll
    for (int r = 0; r < R; r++) shB[phB(base + r)] = vf[r];
    __syncwarp();                          // intra-warp exchange into P2

    // ---------- FWHT#2 P2 ----------
#pragma unroll
    for (int r = 0; r < R; r++) vf[r] = shA[phA(q * 256 + r * 16 + s)];
    fwht4(w);
#pragma unroll
    for (int r = 0; r < R; r++) shA[phA(q * 256 + r * 16 + s)] = vf[r];
    __syncwarp();
#pragma unroll
    for (int r = 0; r < R; r++) vf[r] = shB[phB(q * 256 + r * 16 + s)];
    fwht4(w);
#pragma unroll
    for (int r = 0; r < R; r++) shB[phB(q * 256 + r * 16 + s)] = vf[r];
    bar256(u);

    // ---------- FWHT#2 P3 ----------
#pragma unroll
    for (int r = 0; r < R; r++) vf[r] = shA[phA(u * 4096 + r * 256 + m)];
    fwht4(w);
#pragma unroll
    for (int r = 0; r < R; r++) shA[phA(u * 4096 + r * 256 + m)] = vf[r];
    __syncwarp();
#pragma unroll
    for (int r = 0; r < R; r++) vf[r] = shB[phB(u * 4096 + r * 256 + m)];
    fwht4(w);
#pragma unroll
    for (int r = 0; r < R; r++) shB[phB(u * 4096 + r * 256 + m)] = vf[r];
    __syncthreads();

    // ---------- FWHT#2 P4 + final stores (coalesced STG.32) ----------
#pragma unroll
    for (int r = 0; r < R; r++) vf[r] = shA[phA((r & 3) * 4096 + (r >> 2) * 1024 + t)];
    bf_d1(w); bf_pk<1>(w);
#pragma unroll
    for (int r = 0; r < R; r++) outA[(r & 3) * 4096 + (r >> 2) * 1024 + t] = vf[r];
    __syncwarp();
#pragma unroll
    for (int r = 0; r < R; r++) vf[r] = shB[phB((r & 3) * 4096 + (r >> 2) * 1024 + t)];
    bf_d1(w); bf_pk<1>(w);
#pragma unroll
    for (int r = 0; r < R; r++) outB[(r & 3) * 4096 + (r >> 2) * 1024 + t] = vf[r];
}

extern "C" void kernel_launch(void* const* d_in, const int* in_sizes, int n_in,
                              void* d_out, int out_size)
{
    const float* x  = (const float*)d_in[0];
    const float* B  = (const float*)d_in[1];
    const float* G  = (const float*)d_in[2];
    const int*   Pi = (const int*)d_in[3];
    float* out = (float*)d_out;

    const int rows = in_sizes[0] / L;   // 4096
    const int smem = 2 * L * (int)sizeof(float);   // 128 KB: two rows per CTA

    cudaFuncSetAttribute(ff_kernel, cudaFuncAttributeMaxDynamicSharedMemorySize, smem);

    ff_kernel<<<rows / 2, THREADS, smem>>>(x, B, G, Pi, out);
}

// round 15
// speedup vs baseline: 1.1085x; 1.1085x over previous
#include <cuda_runtime.h>
#include <cstdint>

#define L 16384
#define THREADS 1024
#define R 16

// Swizzle for the R=16 geometry (bijection on [0,16384)).
__device__ __forceinline__ int ph(int i) { return i ^ ((i >> 4) & 31); }

// Named barrier over an aligned 256-thread (8-warp) group.
__device__ __forceinline__ void bar256(int gid) {
    asm volatile("bar.sync %0, %1;" :: "r"(gid + 1), "r"(256) : "memory");
}

// Packed butterfly: (a, b) <- (a+b, a-b) elementwise on float2 (sm_100+ f32x2).
__device__ __forceinline__ void bfly2(float2& a, float2& b) {
    unsigned long long A = *reinterpret_cast<unsigned long long*>(&a);
    unsigned long long B = *reinterpret_cast<unsigned long long*>(&b);
    unsigned long long S, D;
    asm("add.rn.f32x2 %0, %1, %2;" : "=l"(S) : "l"(A), "l"(B));
    asm("sub.rn.f32x2 %0, %1, %2;" : "=l"(D) : "l"(A), "l"(B));
    a = *reinterpret_cast<float2*>(&S);
    b = *reinterpret_cast<float2*>(&D);
}

__device__ __forceinline__ void bf_d1(float2 w[8]) {
#pragma unroll
    for (int j = 0; j < 8; j++) {
        float a = w[j].x, b = w[j].y;
        w[j].x = a + b;
        w[j].y = a - b;
    }
}

template <int D2>
__device__ __forceinline__ void bf_pk(float2 w[8]) {
#pragma unroll
    for (int j = 0; j < 8; j++)
        if ((j & D2) == 0) bfly2(w[j], w[j + D2]);
}

// Full 4-bit in-register FWHT (element bits 0..3): d=1,2,4,8.
__device__ __forceinline__ void fwht4(float2 w[8]) {
    bf_d1(w);
    bf_pk<1>(w);
    bf_pk<2>(w);
    bf_pk<4>(w);
}

// Element bits 4-7 via shuffle: in the P1 layout (i = t*16 + r) these are
// exactly LANE bits 0-3, so the whole P2 pass runs on the shuffle network
// instead of the L1 data path (saves 3 smem ops/elem: P1-st, P2-ld, P2-st).
// Sign rule: lane-bit==0 side -> v + partner; ==1 side -> partner - v.
__device__ __forceinline__ void shfl_stages47(float* vf, int l) {
#pragma unroll
    for (int k = 0; k < 4; k++) {
        const int msk = 1 << k;
        const bool hi = (l & msk) != 0;
#pragma unroll
        for (int r = 0; r < 16; r++) {
            float pv = __shfl_xor_sync(0xffffffffu, vf[r], msk);
            vf[r] = hi ? (pv - vf[r]) : (vf[r] + pv);
        }
    }
}

extern __shared__ float sh[];

// Two rows per CTA, sequential per region (R10 302us schedule), with the
// P1+P2 passes fused via shfl butterflies: per-element smem ops 14 -> 10.
__global__ void __launch_bounds__(THREADS, 1) ff_kernel(
    const float* __restrict__ x,
    const float* __restrict__ Bv,
    const float* __restrict__ Gv,
    const int* __restrict__ Pi,
    float* __restrict__ out)
{
    const int t = threadIdx.x;
    const int l = t & 31;
    // Remaining pass maps (identical to champion):
    //  P3: i = u*4096 + r*256 + m, t=u*256+m (bits 8-11)  exch scope: 256-thr
    //  P4: i = (r&3)*4096 + (r>>2)*1024 + t  (bits 12-13) exch scope: CTA
    const int u = t >> 8, m = t & 255;

    const int rowA = blockIdx.x * 2;
    const float* xrA = x + (size_t)rowA * L;
    const float* xrB = xrA + L;
    float* outA = out + (size_t)rowA * L;
    float* outB = outA + L;

    float* const shA = sh;
    float* const shB = sh + L;

    float2 w[8];
    float* vf = reinterpret_cast<float*>(w);
    const int base = t * R;

    constexpr float SC = 1.0f / 16384.0f;

    // ---------- FWHT#1: load + bits 0-3 (reg) + bits 4-7 (shfl) + store ----------
#pragma unroll
    for (int c = 0; c < 4; c++) {
        float4 xa = *reinterpret_cast<const float4*>(xrA + base + c * 4);
        float4 bv = *reinterpret_cast<const float4*>(Bv + base + c * 4);
        vf[c * 4 + 0] = xa.x * bv.x; vf[c * 4 + 1] = xa.y * bv.y;
        vf[c * 4 + 2] = xa.z * bv.z; vf[c * 4 + 3] = xa.w * bv.w;
    }
    fwht4(w);
    shfl_stages47(vf, l);
#pragma unroll
    for (int r = 0; r < R; r++) shA[ph(base + r)] = vf[r];

#pragma unroll
    for (int c = 0; c < 4; c++) {
        float4 xb = *reinterpret_cast<const float4*>(xrB + base + c * 4);
        float4 bv = *reinterpret_cast<const float4*>(Bv + base + c * 4);
        vf[c * 4 + 0] = xb.x * bv.x; vf[c * 4 + 1] = xb.y * bv.y;
        vf[c * 4 + 2] = xb.z * bv.z; vf[c * 4 + 3] = xb.w * bv.w;
    }
    fwht4(w);
    shfl_stages47(vf, l);
#pragma unroll
    for (int r = 0; r < R; r++) shB[ph(base + r)] = vf[r];
    bar256(u);                             // writers for a P3 reader span 256 threads

    // ---------- P3 (bits 8-11) ----------
#pragma unroll
    for (int r = 0; r < R; r++) vf[r] = shA[ph(u * 4096 + r * 256 + m)];
    fwht4(w);
#pragma unroll
    for (int r = 0; r < R; r++) shA[ph(u * 4096 + r * 256 + m)] = vf[r];
#pragma unroll
    for (int r = 0; r < R; r++) vf[r] = shB[ph(u * 4096 + r * 256 + m)];
    fwht4(w);
#pragma unroll
    for (int r = 0; r < R; r++) shB[ph(u * 4096 + r * 256 + m)] = vf[r];
    __syncthreads();

    // ---------- P4 (bits 12-13) ----------
#pragma unroll
    for (int r = 0; r < R; r++) vf[r] = shA[ph((r & 3) * 4096 + (r >> 2) * 1024 + t)];
    bf_d1(w); bf_pk<1>(w);
#pragma unroll
    for (int r = 0; r < R; r++) shA[ph((r & 3) * 4096 + (r >> 2) * 1024 + t)] = vf[r];
#pragma unroll
    for (int r = 0; r < R; r++) vf[r] = shB[ph((r & 3) * 4096 + (r >> 2) * 1024 + t)];
    bf_d1(w); bf_pk<1>(w);
#pragma unroll
    for (int r = 0; r < R; r++) shB[ph((r & 3) * 4096 + (r >> 2) * 1024 + t)] = vf[r];
    __syncthreads();                       // gather reads arbitrary positions

    // ---------- gather + FWHT#2 bits 0-7, row A ----------
#pragma unroll
    for (int c = 0; c < 4; c++) {
        int4   p = *reinterpret_cast<const int4*>(Pi + base + c * 4);
        float4 g = *reinterpret_cast<const float4*>(Gv + base + c * 4);
        vf[c * 4 + 0] = shA[ph(p.x)] * (g.x * SC);
        vf[c * 4 + 1] = shA[ph(p.y)] * (g.y * SC);
        vf[c * 4 + 2] = shA[ph(p.z)] * (g.z * SC);
        vf[c * 4 + 3] = shA[ph(p.w)] * (g.w * SC);
    }
    fwht4(w);
    shfl_stages47(vf, l);
    __syncthreads();                       // all row-A gathers complete
#pragma unroll
    for (int r = 0; r < R; r++) shA[ph(base + r)] = vf[r];

    // ---------- gather + FWHT#2 bits 0-7, row B ----------
#pragma unroll
    for (int c = 0; c < 4; c++) {
        int4   p = *reinterpret_cast<const int4*>(Pi + base + c * 4);
        float4 g = *reinterpret_cast<const float4*>(Gv + base + c * 4);
        vf[c * 4 + 0] = shB[ph(p.x)] * (g.x * SC);
        vf[c * 4 + 1] = shB[ph(p.y)] * (g.y * SC);
        vf[c * 4 + 2] = shB[ph(p.z)] * (g.z * SC);
        vf[c * 4 + 3] = shB[ph(p.w)] * (g.w * SC);
    }
    fwht4(w);
    shfl_stages47(vf, l);
    __syncthreads();                       // all row-B gathers complete
#pragma unroll
    for (int r = 0; r < R; r++) shB[ph(base + r)] = vf[r];
    bar256(u);

    // ---------- FWHT#2 P3 ----------
#pragma unroll
    for (int r = 0; r < R; r++) vf[r] = shA[ph(u * 4096 + r * 256 + m)];
    fwht4(w);
#pragma unroll
    for (int r = 0; r < R; r++) shA[ph(u * 4096 + r * 256 + m)] = vf[r];
#pragma unroll
    for (int r = 0; r < R; r++) vf[r] = shB[ph(u * 4096 + r * 256 + m)];
    fwht4(w);
#pragma unroll
    for (int r = 0; r < R; r++) shB[ph(u * 4096 + r * 256 + m)] = vf[r];
    __syncthreads();

    // ---------- FWHT#2 P4 + final stores (coalesced STG.32) ----------
#pragma unroll
    for (int r = 0; r < R; r++) vf[r] = shA[ph((r & 3) * 4096 + (r >> 2) * 1024 + t)];
    bf_d1(w); bf_pk<1>(w);
#pragma unroll
    for (int r = 0; r < R; r++) outA[(r & 3) * 4096 + (r >> 2) * 1024 + t] = vf[r];
#pragma unroll
    for (int r = 0; r < R; r++) vf[r] = shB[ph((r & 3) * 4096 + (r >> 2) * 1024 + t)];
    bf_d1(w); bf_pk<1>(w);
#pragma unroll
    for (int r = 0; r < R; r++) outB[(r & 3) * 4096 + (r >> 2) * 1024 + t] = vf[r];
}

extern "C" void kernel_launch(void* const* d_in, const int* in_sizes, int n_in,
                              void* d_out, int out_size)
{
    const float* x  = (const float*)d_in[0];
    const float* B  = (const float*)d_in[1];
    const float* G  = (const float*)d_in[2];
    const int*   Pi = (const int*)d_in[3];
    float* out = (float*)d_out;

    const int rows = in_sizes[0] / L;   // 4096
    const int smem = 2 * L * (int)sizeof(float);   // 128 KB: two rows per CTA

    cudaFuncSetAttribute(ff_kernel, cudaFuncAttributeMaxDynamicSharedMemorySize, smem);

    ff_kernel<<<rows / 2, THREADS, smem>>>(x, B, G, Pi, out);
}

// round 16
// speedup vs baseline: 1.3564x; 1.2236x over previous
#include <cuda_runtime.h>
#include <cuda_fp16.h>
#include <cstdint>

#define L 16384
#define THREADS 1024

// Uniform word-swizzle for all 8192-word fp16x2 row buffers.
// Verified conflict-free for every access pattern below (bit-level, per shape).
__device__ __forceinline__ int SW(int wi) {
    return wi ^ ((wi >> 3) & 0x18) ^ ((wi >> 5) & 7);
}

__device__ __forceinline__ void bar256(int gid) {
    asm volatile("bar.sync %0, %1;" :: "r"(gid + 1), "r"(256) : "memory");
}
__device__ __forceinline__ void bar512(int gid) {
    asm volatile("bar.sync %0, %1;" :: "r"(gid + 5), "r"(512) : "memory");
}

// fp32 packed butterflies (sm_100+ f32x2) — arithmetic stays fp32 end to end.
__device__ __forceinline__ void bfly2(float2& a, float2& b) {
    unsigned long long A = *reinterpret_cast<unsigned long long*>(&a);
    unsigned long long B = *reinterpret_cast<unsigned long long*>(&b);
    unsigned long long S, D;
    asm("add.rn.f32x2 %0, %1, %2;" : "=l"(S) : "l"(A), "l"(B));
    asm("sub.rn.f32x2 %0, %1, %2;" : "=l"(D) : "l"(A), "l"(B));
    a = *reinterpret_cast<float2*>(&S);
    b = *reinterpret_cast<float2*>(&D);
}
__device__ __forceinline__ void bf_d1(float2 w[8]) {
#pragma unroll
    for (int j = 0; j < 8; j++) {
        float a = w[j].x, b = w[j].y;
        w[j].x = a + b; w[j].y = a - b;
    }
}
template <int D2>
__device__ __forceinline__ void bf_pk(float2 w[8]) {
#pragma unroll
    for (int j = 0; j < 8; j++)
        if ((j & D2) == 0) bfly2(w[j], w[j + D2]);
}
// element-index dists 1,2,4,8 (P1)
__device__ __forceinline__ void fwht4(float2 w[8]) { bf_d1(w); bf_pk<1>(w); bf_pk<2>(w); bf_pk<4>(w); }
// element-index dists 2,4,8 only (P2/P3/P4: lowest reg bit is the pack passenger)
__device__ __forceinline__ void fwht3h(float2 w[8]) { bf_pk<1>(w); bf_pk<2>(w); bf_pk<4>(w); }

__device__ __forceinline__ uint32_t packh(float lo, float hi) {
    __half2 h = __floats2half2_rn(lo, hi);
    return *reinterpret_cast<uint32_t*>(&h);
}
__device__ __forceinline__ float2 unpkh(uint32_t u) {
    __half2 h = *reinterpret_cast<__half2*>(&u);
    return __half22float2(h);
}

extern __shared__ uint32_t shw[];   // bufA: [0,8192), bufB: [8192,16384)

// fp16x2-packed exchange pipeline: fp32 register math, half-width smem words.
// 5-pass chain, pack bits 3/6/9/12; per-pass write set == read set (in-place).
__global__ void __launch_bounds__(THREADS, 1) ff_kernel(
    const float* __restrict__ x,
    const float* __restrict__ Bv,
    const float* __restrict__ Gv,
    const int* __restrict__ Pi,
    float* __restrict__ out)
{
    const int t = threadIdx.x;
    const int lo3 = t & 7,   hi7 = t >> 3;   // P2 fields
    const int lo6 = t & 63,  hh  = t >> 6;   // P3 fields
    const int lo9 = t & 511, top = t >> 9;   // P4 fields

    const int rowA = blockIdx.x * 2;
    const float* xrA = x + (size_t)rowA * L;
    const float* xrB = xrA + L;
    float* outA = out + (size_t)rowA * L;
    float* outB = outA + L;

    uint32_t* const bufA = shw;
    uint32_t* const bufB = shw + 8192;

    float2 w[8];
    float* vf = reinterpret_cast<float*>(w);
    const int base = t * 16;
    constexpr float SC = 1.0f / 16384.0f;

    // ---- pass bodies (word formulas verified by end-to-end element trace) ----
#define P1_STORE(U)                                                         \
    do { _Pragma("unroll") for (int j = 0; j < 8; j++)                      \
        (U)[SW(t * 8 + j)] = packh(vf[j], vf[j + 8]); } while (0)

#define P2_PASS(U)                                                          \
    do {                                                                    \
        _Pragma("unroll") for (int j = 0; j < 8; j++)                       \
            w[j] = unpkh((U)[SW(hi7 * 64 + j * 8 + lo3)]);                  \
        fwht3h(w);                                                          \
        _Pragma("unroll") for (int j = 0; j < 8; j++)                       \
            (U)[SW(hi7 * 64 + j * 8 + lo3)] = packh(vf[j], vf[j + 8]);      \
    } while (0)

#define P3_PASS(U)                                                          \
    do {                                                                    \
        _Pragma("unroll") for (int j = 0; j < 8; j++)                       \
            w[j] = unpkh((U)[SW(hh * 512 + j * 64 + lo6)]);                 \
        fwht3h(w);                                                          \
        _Pragma("unroll") for (int j = 0; j < 8; j++)                       \
            (U)[SW(hh * 512 + j * 64 + lo6)] = packh(vf[j], vf[j + 8]);     \
    } while (0)

#define P4_PASS(U)                                                          \
    do {                                                                    \
        _Pragma("unroll") for (int j = 0; j < 8; j++)                       \
            w[j] = unpkh((U)[SW(top * 4096 + j * 512 + lo9)]);              \
        fwht3h(w);                                                          \
        _Pragma("unroll") for (int j = 0; j < 8; j++)                       \
            (U)[SW(top * 4096 + j * 512 + lo9)] = packh(vf[j], vf[j + 8]);  \
    } while (0)

    // P5: regs = bits 12,13 (butterfly bit 13 only; 12 already done at P4);
    // vf index = d*4 + p, d = i>>12, p = (i>>10)&3, i = d*4096 + p*1024 + t.
#define P5_LOAD(U)                                                          \
    do { _Pragma("unroll") for (int dd = 0; dd < 2; dd++)                   \
         _Pragma("unroll") for (int p = 0; p < 4; p++) {                    \
            float2 f = unpkh((U)[SW(dd * 4096 + p * 1024 + t)]);            \
            vf[dd * 8 + p] = f.x; vf[dd * 8 + 4 + p] = f.y; } } while (0)

#define P5_STORE(U)                                                         \
    do { _Pragma("unroll") for (int dd = 0; dd < 2; dd++)                   \
         _Pragma("unroll") for (int p = 0; p < 4; p++)                      \
            (U)[SW(dd * 4096 + p * 1024 + t)] =                             \
                packh(vf[dd * 8 + p], vf[dd * 8 + 4 + p]); } while (0)

#define GATHER1(U, e, gv)                                                   \
    ([&]() -> float {                                                       \
        uint32_t u = (U)[SW(((e) >> 13) * 4096 + ((e) & 4095))];            \
        __half2 h = *reinterpret_cast<__half2*>(&u);                        \
        float val = (((e) >> 12) & 1) ? __high2float(h) : __low2float(h);   \
        return val * (gv);                                                  \
    }())

    // ================= FWHT #1 =================
    // P1: global load x*B, butterfly bits 0-3, packed store (pairs by bit 3)
#pragma unroll
    for (int c = 0; c < 4; c++) {
        float4 xa = *reinterpret_cast<const float4*>(xrA + base + c * 4);
        float4 bv = *reinterpret_cast<const float4*>(Bv + base + c * 4);
        vf[c * 4 + 0] = xa.x * bv.x; vf[c * 4 + 1] = xa.y * bv.y;
        vf[c * 4 + 2] = xa.z * bv.z; vf[c * 4 + 3] = xa.w * bv.w;
    }
    fwht4(w);
    P1_STORE(bufA);
#pragma unroll
    for (int c = 0; c < 4; c++) {
        float4 xb = *reinterpret_cast<const float4*>(xrB + base + c * 4);
        float4 bv = *reinterpret_cast<const float4*>(Bv + base + c * 4);
        vf[c * 4 + 0] = xb.x * bv.x; vf[c * 4 + 1] = xb.y * bv.y;
        vf[c * 4 + 2] = xb.z * bv.z; vf[c * 4 + 3] = xb.w * bv.w;
    }
    fwht4(w);
    P1_STORE(bufB);
    __syncwarp();                        // P1->P2 scope: 8-thread groups

    P2_PASS(bufA); P2_PASS(bufB); bar256(t >> 8);    // P2->P3 scope: 64
    P3_PASS(bufA); P3_PASS(bufB); bar512(t >> 9);    // P3->P4 scope: 512
    P4_PASS(bufA); P4_PASS(bufB); __syncthreads();   // P4->P5 scope: CTA

    P5_LOAD(bufA); bf_pk<4>(w); P5_STORE(bufA);      // butterfly bit 13
    P5_LOAD(bufB); bf_pk<4>(w); P5_STORE(bufB);
    __syncthreads();                     // gather reads arbitrary positions

    // ---- permutation gather + gain + scale, then FWHT#2 P1, per row ----
#pragma unroll
    for (int c = 0; c < 4; c++) {
        int4   p = *reinterpret_cast<const int4*>(Pi + base + c * 4);
        float4 g = *reinterpret_cast<const float4*>(Gv + base + c * 4);
        vf[c * 4 + 0] = GATHER1(bufA, p.x, g.x * SC);
        vf[c * 4 + 1] = GATHER1(bufA, p.y, g.y * SC);
        vf[c * 4 + 2] = GATHER1(bufA, p.z, g.z * SC);
        vf[c * 4 + 3] = GATHER1(bufA, p.w, g.w * SC);
    }
    fwht4(w);
    __syncthreads();                     // all row-A gathers complete
    P1_STORE(bufA);
#pragma unroll
    for (int c = 0; c < 4; c++) {
        int4   p = *reinterpret_cast<const int4*>(Pi + base + c * 4);
        float4 g = *reinterpret_cast<const float4*>(Gv + base + c * 4);
        vf[c * 4 + 0] = GATHER1(bufB, p.x, g.x * SC);
        vf[c * 4 + 1] = GATHER1(bufB, p.y, g.y * SC);
        vf[c * 4 + 2] = GATHER1(bufB, p.z, g.z * SC);
        vf[c * 4 + 3] = GATHER1(bufB, p.w, g.w * SC);
    }
    fwht4(w);
    __syncthreads();                     // all row-B gathers complete
    P1_STORE(bufB);
    __syncwarp();

    // ================= FWHT #2 =================
    P2_PASS(bufA); P2_PASS(bufB); bar256(t >> 8);
    P3_PASS(bufA); P3_PASS(bufB); bar512(t >> 9);
    P4_PASS(bufA); P4_PASS(bufB); __syncthreads();

    // P5 + final store: i = d*4096 + p*1024 + t -> stride-1 coalesced STG
    P5_LOAD(bufA); bf_pk<4>(w);
#pragma unroll
    for (int d = 0; d < 4; d++)
#pragma unroll
        for (int p = 0; p < 4; p++)
            outA[d * 4096 + p * 1024 + t] = vf[d * 4 + p];
    P5_LOAD(bufB); bf_pk<4>(w);
#pragma unroll
    for (int d = 0; d < 4; d++)
#pragma unroll
        for (int p = 0; p < 4; p++)
            outB[d * 4096 + p * 1024 + t] = vf[d * 4 + p];

#undef P1_STORE
#undef P2_PASS
#undef P3_PASS
#undef P4_PASS
#undef P5_LOAD
#undef P5_STORE
#undef GATHER1
}

extern "C" void kernel_launch(void* const* d_in, const int* in_sizes, int n_in,
                              void* d_out, int out_size)
{
    const float* x  = (const float*)d_in[0];
    const float* B  = (const float*)d_in[1];
    const float* G  = (const float*)d_in[2];
    const int*   Pi = (const int*)d_in[3];
    float* out = (float*)d_out;

    const int rows = in_sizes[0] / L;   // 4096
    const int smem = 2 * 8192 * (int)sizeof(uint32_t);   // 64 KB (two fp16x2 rows)

    cudaFuncSetAttribute(ff_kernel, cudaFuncAttributeMaxDynamicSharedMemorySize, smem);

    ff_kernel<<<rows / 2, THREADS, smem>>>(x, B, G, Pi, out);
}

// round 17
// speedup vs baseline: 1.4886x; 1.0974x over previous
#include <cuda_runtime.h>
#include <cuda_fp16.h>
#include <cstdint>

#define L 16384
#define THREADS 1024
#define ROWS_PER_CTA 4

// Uniform word-swizzle for all 8192-word fp16x2 row buffers (verified per shape).
__device__ __forceinline__ int SW(int wi) {
    return wi ^ ((wi >> 3) & 0x18) ^ ((wi >> 5) & 7);
}

__device__ __forceinline__ void bar256(int gid) {
    asm volatile("bar.sync %0, %1;" :: "r"(gid + 1), "r"(256) : "memory");
}
__device__ __forceinline__ void bar512(int gid) {
    asm volatile("bar.sync %0, %1;" :: "r"(gid + 5), "r"(512) : "memory");
}

// fp32 packed butterflies (sm_100+ f32x2) — register math stays fp32.
__device__ __forceinline__ void bfly2(float2& a, float2& b) {
    unsigned long long A = *reinterpret_cast<unsigned long long*>(&a);
    unsigned long long B = *reinterpret_cast<unsigned long long*>(&b);
    unsigned long long S, D;
    asm("add.rn.f32x2 %0, %1, %2;" : "=l"(S) : "l"(A), "l"(B));
    asm("sub.rn.f32x2 %0, %1, %2;" : "=l"(D) : "l"(A), "l"(B));
    a = *reinterpret_cast<float2*>(&S);
    b = *reinterpret_cast<float2*>(&D);
}
__device__ __forceinline__ void bf_d1(float2 w[8]) {
#pragma unroll
    for (int j = 0; j < 8; j++) {
        float a = w[j].x, b = w[j].y;
        w[j].x = a + b; w[j].y = a - b;
    }
}
template <int D2>
__device__ __forceinline__ void bf_pk(float2 w[8]) {
#pragma unroll
    for (int j = 0; j < 8; j++)
        if ((j & D2) == 0) bfly2(w[j], w[j + D2]);
}
__device__ __forceinline__ void fwht4(float2 w[8]) { bf_d1(w); bf_pk<1>(w); bf_pk<2>(w); bf_pk<4>(w); }
__device__ __forceinline__ void fwht3h(float2 w[8]) { bf_pk<1>(w); bf_pk<2>(w); bf_pk<4>(w); }

__device__ __forceinline__ uint32_t packh(float lo, float hi) {
    __half2 h = __floats2half2_rn(lo, hi);
    return *reinterpret_cast<uint32_t*>(&h);
}
__device__ __forceinline__ float2 unpkh(uint32_t u) {
    __half2 h = *reinterpret_cast<__half2*>(&u);
    return __half22float2(h);
}

extern __shared__ uint32_t shw[];   // 4 row buffers x 8192 words (128 KB)

// fp16x2 exchange pipeline (proven 254us @ 2 rows), now 4 rows/CTA: each
// pass-chain barrier serves 4 rows. Rolled row loops keep regs + I$ flat.
__global__ void __launch_bounds__(THREADS, 1) ff_kernel(
    const float* __restrict__ x,
    const float* __restrict__ Bv,
    const float* __restrict__ Gv,
    const int* __restrict__ Pi,
    float* __restrict__ out)
{
    const int t = threadIdx.x;
    const int lo3 = t & 7,   hi7 = t >> 3;   // P2 fields
    const int lo6 = t & 63,  hh  = t >> 6;   // P3 fields
    const int lo9 = t & 511, top = t >> 9;   // P4 fields

    const int row0 = blockIdx.x * ROWS_PER_CTA;
    const float* xr0 = x + (size_t)row0 * L;
    float* out0 = out + (size_t)row0 * L;

    float2 w[8];
    float* vf = reinterpret_cast<float*>(w);
    const int base = t * 16;
    constexpr float SC = 1.0f / 16384.0f;

#define P1_STORE(U)                                                         \
    do { _Pragma("unroll") for (int j = 0; j < 8; j++)                      \
        (U)[SW(t * 8 + j)] = packh(vf[j], vf[j + 8]); } while (0)

#define P2_PASS(U)                                                          \
    do {                                                                    \
        _Pragma("unroll") for (int j = 0; j < 8; j++)                       \
            w[j] = unpkh((U)[SW(hi7 * 64 + j * 8 + lo3)]);                  \
        fwht3h(w);                                                          \
        _Pragma("unroll") for (int j = 0; j < 8; j++)                       \
            (U)[SW(hi7 * 64 + j * 8 + lo3)] = packh(vf[j], vf[j + 8]);      \
    } while (0)

#define P3_PASS(U)                                                          \
    do {                                                                    \
        _Pragma("unroll") for (int j = 0; j < 8; j++)                       \
            w[j] = unpkh((U)[SW(hh * 512 + j * 64 + lo6)]);                 \
        fwht3h(w);                                                          \
        _Pragma("unroll") for (int j = 0; j < 8; j++)                       \
            (U)[SW(hh * 512 + j * 64 + lo6)] = packh(vf[j], vf[j + 8]);     \
    } while (0)

#define P4_PASS(U)                                                          \
    do {                                                                    \
        _Pragma("unroll") for (int j = 0; j < 8; j++)                       \
            w[j] = unpkh((U)[SW(top * 4096 + j * 512 + lo9)]);              \
        fwht3h(w);                                                          \
        _Pragma("unroll") for (int j = 0; j < 8; j++)                       \
            (U)[SW(top * 4096 + j * 512 + lo9)] = packh(vf[j], vf[j + 8]);  \
    } while (0)

#define P5_LOAD(U)                                                          \
    do { _Pragma("unroll") for (int dd = 0; dd < 2; dd++)                   \
         _Pragma("unroll") for (int p = 0; p < 4; p++) {                    \
            float2 f = unpkh((U)[SW(dd * 4096 + p * 1024 + t)]);            \
            vf[dd * 8 + p] = f.x; vf[dd * 8 + 4 + p] = f.y; } } while (0)

#define P5_STORE(U)                                                         \
    do { _Pragma("unroll") for (int dd = 0; dd < 2; dd++)                   \
         _Pragma("unroll") for (int p = 0; p < 4; p++)                      \
            (U)[SW(dd * 4096 + p * 1024 + t)] =                             \
                packh(vf[dd * 8 + p], vf[dd * 8 + 4 + p]); } while (0)

#define GATHER1(U, e, gv)                                                   \
    ([&]() -> float {                                                       \
        uint32_t u = (U)[SW(((e) >> 13) * 4096 + ((e) & 4095))];            \
        __half2 h = *reinterpret_cast<__half2*>(&u);                        \
        float val = (((e) >> 12) & 1) ? __high2float(h) : __low2float(h);   \
        return val * (gv);                                                  \
    }())

    // ================= FWHT #1 =================
    // P1: global load x*B, butterfly bits 0-3, packed store (pairs by bit 3)
#pragma unroll 1
    for (int k = 0; k < ROWS_PER_CTA; k++) {
        const float* xr = xr0 + (size_t)k * L;
        uint32_t* buf = shw + k * 8192;
#pragma unroll
        for (int c = 0; c < 4; c++) {
            float4 xv = *reinterpret_cast<const float4*>(xr + base + c * 4);
            float4 bv = *reinterpret_cast<const float4*>(Bv + base + c * 4);
            vf[c * 4 + 0] = xv.x * bv.x; vf[c * 4 + 1] = xv.y * bv.y;
            vf[c * 4 + 2] = xv.z * bv.z; vf[c * 4 + 3] = xv.w * bv.w;
        }
        fwht4(w);
        P1_STORE(buf);
    }
    __syncwarp();                        // P1->P2 scope: 8-thread groups

#pragma unroll 1
    for (int k = 0; k < ROWS_PER_CTA; k++) { uint32_t* buf = shw + k * 8192; P2_PASS(buf); }
    bar256(t >> 8);                      // P2->P3 scope: 64
#pragma unroll 1
    for (int k = 0; k < ROWS_PER_CTA; k++) { uint32_t* buf = shw + k * 8192; P3_PASS(buf); }
    bar512(t >> 9);                      // P3->P4 scope: 512
#pragma unroll 1
    for (int k = 0; k < ROWS_PER_CTA; k++) { uint32_t* buf = shw + k * 8192; P4_PASS(buf); }
    __syncthreads();                     // P4->P5 scope: CTA
#pragma unroll 1
    for (int k = 0; k < ROWS_PER_CTA; k++) {
        uint32_t* buf = shw + k * 8192;
        P5_LOAD(buf); bf_pk<4>(w); P5_STORE(buf);   // butterfly bit 13
    }
    __syncthreads();                     // gather reads arbitrary positions

    // ---- permutation gather + gain + scale, then FWHT#2 P1, per row ----
#pragma unroll 1
    for (int k = 0; k < ROWS_PER_CTA; k++) {
        uint32_t* buf = shw + k * 8192;
#pragma unroll
        for (int c = 0; c < 4; c++) {
            int4   p = *reinterpret_cast<const int4*>(Pi + base + c * 4);
            float4 g = *reinterpret_cast<const float4*>(Gv + base + c * 4);
            vf[c * 4 + 0] = GATHER1(buf, p.x, g.x * SC);
            vf[c * 4 + 1] = GATHER1(buf, p.y, g.y * SC);
            vf[c * 4 + 2] = GATHER1(buf, p.z, g.z * SC);
            vf[c * 4 + 3] = GATHER1(buf, p.w, g.w * SC);
        }
        fwht4(w);
        __syncthreads();                 // all gathers of row k complete
        P1_STORE(buf);
    }
    __syncwarp();                        // P1 stores visible to 8-thread groups

    // ================= FWHT #2 =================
#pragma unroll 1
    for (int k = 0; k < ROWS_PER_CTA; k++) { uint32_t* buf = shw + k * 8192; P2_PASS(buf); }
    bar256(t >> 8);
#pragma unroll 1
    for (int k = 0; k < ROWS_PER_CTA; k++) { uint32_t* buf = shw + k * 8192; P3_PASS(buf); }
    bar512(t >> 9);
#pragma unroll 1
    for (int k = 0; k < ROWS_PER_CTA; k++) { uint32_t* buf = shw + k * 8192; P4_PASS(buf); }
    __syncthreads();

    // P5 + final store: i = d*4096 + p*1024 + t -> stride-1 coalesced STG
#pragma unroll 1
    for (int k = 0; k < ROWS_PER_CTA; k++) {
        uint32_t* buf = shw + k * 8192;
        float* outr = out0 + (size_t)k * L;
        P5_LOAD(buf); bf_pk<4>(w);
#pragma unroll
        for (int d = 0; d < 4; d++)
#pragma unroll
            for (int p = 0; p < 4; p++)
                outr[d * 4096 + p * 1024 + t] = vf[d * 4 + p];
    }

#undef P1_STORE
#undef P2_PASS
#undef P3_PASS
#undef P4_PASS
#undef P5_LOAD
#undef P5_STORE
#undef GATHER1
}

extern "C" void kernel_launch(void* const* d_in, const int* in_sizes, int n_in,
                              void* d_out, int out_size)
{
    const float* x  = (const float*)d_in[0];
    const float* B  = (const float*)d_in[1];
    const float* G  = (const float*)d_in[2];
    const int*   Pi = (const int*)d_in[3];
    float* out = (float*)d_out;

    const int rows = in_sizes[0] / L;   // 4096
    const int smem = ROWS_PER_CTA * 8192 * (int)sizeof(uint32_t);   // 128 KB

    cudaFuncSetAttribute(ff_kernel, cudaFuncAttributeMaxDynamicSharedMemorySize, smem);

    ff_kernel<<<rows / ROWS_PER_CTA, THREADS, smem>>>(x, B, G, Pi, out);
}